// round 12
// baseline (speedup 1.0000x reference)
#include <cuda_runtime.h>

// BlurOutwards: out = (1/20) * sum_{i=0}^{19} D^i(x), D = 3x3 max, zero padding.
// Iterated zero-padded dilation == iterated 3x3 max on the zero-extended image;
// composes across passes: D^{a+b}(x) = D^b(D^a(x)).
//
// Three chained register-pipeline passes (7 + 7 + 5 levels), 1 px/thread,
// TPB=512, 2 CTAs/SM, two rows per barrier, corner-square identity, float2
// edge exchange — R11 semantics — plus MODULO-SCHEDULED OUTER LOOP:
// two 2-row steps per outer iteration with double-buffered state, so all
// 1-step delay buffers are SSA flow (no rotation MOVs) and smem parity is a
// compile-time constant.

#define IMH   512
#define IMW   512
#define TPB   512
#define NW    (TPB / 32)       // 16 warps
#define SEGS  3
#define MAX_PLANES 96

__device__ float g_scrA[MAX_PLANES * IMH * IMW];
__device__ float g_scrB[MAX_PLANES * IMH * IMW];

// One 2-row step. Reads per-level state from *_i, writes next state to *_o.
// qhi is phase-local (value written here is consumed 2 global steps later,
// i.e. by the same phase next outer iteration) — read-then-overwrite in place.
template<int NLEV, bool FIRST, bool WRITE_Y, bool FINAL, int PAR>
__device__ __forceinline__ void two_row_step(
    int t, int r0, int r1,
    const float* __restrict__ ip, const float* sum_in,
    float* sum_out, float* __restrict__ y_out, size_t pbase,
    int col, int warp, bool isL, bool isR,
    float2 (*eE)[2][NW + 2][8],
    const float (&pAi)[NLEV], const float (&pBi)[NLEV],
    const float (&h1i)[NLEV], const float (&h2i)[NLEV],
    const float (&qloi)[NLEV],
    float (&qhi)[NLEV],
    float (&pAo)[NLEV], float (&pBo)[NLEV],
    float (&h1o)[NLEV], float (&h2o)[NLEV],
    float (&qloo)[NLEV])
{
    float2 (*eRd)[NW + 2][8] = eE[PAR];
    float2 (*eWr)[NW + 2][8] = eE[PAR ^ 1];

    // Ingest input rows t, t+1 (zero-extended).
    float u0 = 0.0f, u1 = 0.0f;
    if ((unsigned)t       < (unsigned)IMH) u0 = ip[(size_t)t       * IMW + col];
    if ((unsigned)(t + 1) < (unsigned)IMH) u1 = ip[(size_t)(t + 1) * IMW + col];
    float q0 = FIRST ? u0 : 0.0f;
    float q1 = FIRST ? u1 : 0.0f;

#pragma unroll
    for (int i = 0; i < NLEV; ++i) {
        float a = pAi[i], b = pBi[i];
        float la = __shfl_up_sync(0xffffffffu, a, 1);
        float ra = __shfl_down_sync(0xffffffffu, a, 1);
        float lb = __shfl_up_sync(0xffffffffu, b, 1);
        float rb = __shfl_down_sync(0xffffffffu, b, 1);
        if (isL) { float2 e = eRd[0][warp][i];     la = e.x; lb = e.y; }
        if (isR) { float2 e = eRd[1][warp + 2][i]; ra = e.x; rb = e.y; }

        float yA, yB;
        if (FIRST && i == 0) {
            // Raw-image level: full separable 3x3 max.
            float HA = fmaxf(fmaxf(la, ra), a);
            float HB = fmaxf(fmaxf(lb, rb), b);
            yA = fmaxf(h2i[i], HA);
            float m2 = fmaxf(h1i[i], HA);
            yB = fmaxf(m2, HB);
            h2o[i] = fmaxf(HA, HB);
            h1o[i] = HB;
        } else {
            // Corner identity: input is already a square max (radius >= 1).
            float HA = fmaxf(la, ra);
            float HB = fmaxf(lb, rb);
            yA = fmaxf(h2i[i], HA);
            yB = fmaxf(h1i[i], HB);
            h2o[i] = HA;
            h1o[i] = HB;
        }

        // Sum stream: q1 delayed 2 steps (phase-local qhi), q0 delayed 1 step.
        float sA = qhi[i] + yA;
        float sB = qloi[i] + yB;
        qhi[i]  = q1;
        qloo[i] = q0;

        // Hand-off to next level + edge publication for next step.
        pAo[i] = u0;  pBo[i] = u1;
        if (isL) eWr[1][warp + 1][i] = make_float2(u0, u1);
        if (isR) eWr[0][warp + 1][i] = make_float2(u0, u1);
        u0 = yA;  u1 = yB;
        q0 = sA;  q1 = sB;
    }

    // q0/q1 = s_NLEV rows (t-DELAY, t+1-DELAY); u0/u1 = y_NLEV same rows.
    const int DELAY = 3 * NLEV;
    const int orow = t - DELAY;
    if (orow >= r0 && orow < r1) {
        const size_t idx = pbase + (size_t)orow * IMW + col;
        float s = q0;
        if (!FIRST) s += sum_in[idx];
        sum_out[idx] = FINAL ? s * 0.05f : s;
        if (WRITE_Y) y_out[idx] = u0;
    }
    const int orow2 = orow + 1;
    if (orow2 >= r0 && orow2 < r1) {
        const size_t idx = pbase + (size_t)orow2 * IMW + col;
        float s = q1;
        if (!FIRST) s += sum_in[idx];
        sum_out[idx] = FINAL ? s * 0.05f : s;
        if (WRITE_Y) y_out[idx] = u1;
    }

    __syncthreads();  // separates this step's edge writes from next step's reads
}

template<int NLEV, bool FIRST, bool WRITE_Y, bool FINAL>
__global__ __launch_bounds__(TPB, 2)
void blur_pass_kernel(const float* __restrict__ in,
                      const float* sum_in,
                      float* sum_out,
                      float* __restrict__ y_out)
{
    const int plane = blockIdx.x;
    const int seg   = blockIdx.y;

    const int r0 = (IMH * seg) / SEGS;
    const int r1 = (IMH * (seg + 1)) / SEGS;

    const size_t pbase = (size_t)plane * IMH * IMW;
    const float* ip = in + pbase;

    const int col  = threadIdx.x;
    const int lane = col & 31;
    const int warp = col >> 5;
    const bool isL = (lane == 0);
    const bool isR = (lane == 31);

    // Edge exchange: [parity][side][warpSlot][level], float2 = (rowA, rowB).
    //   side 0 = right edges (lane31), side 1 = left edges (lane0).
    //   warpSlot = warp+1; slots 0 and NW+1 stay zero (image-border guard).
    __shared__ float2 eE[2][2][NW + 2][8];
    for (int k = threadIdx.x; k < 2 * 2 * (NW + 2) * 8 * 2; k += TPB)
        ((float*)&eE[0][0][0][0])[k] = 0.0f;
    __syncthreads();

    // Loop-carried per-level state (zero == zero-extension above the strip).
    float pA_s[NLEV], pB_s[NLEV], h1_s[NLEV], h2_s[NLEV], qlo_s[NLEV];
    float qhiA[NLEV], qhiB[NLEV];
#pragma unroll
    for (int i = 0; i < NLEV; ++i) {
        pA_s[i]=0.f; pB_s[i]=0.f; h1_s[i]=0.f; h2_s[i]=0.f; qlo_s[i]=0.f;
        qhiA[i]=0.f; qhiB[i]=0.f;
    }

    const int DELAY = 3 * NLEV;
    const int T0    = r0 - NLEV;              // spatial warmup

    for (int t = T0; t - DELAY <= r1 - 1; t += 4) {
        // Temps: pure SSA flow from step A to step B (no loop-carried MOVs).
        float pA_t[NLEV], pB_t[NLEV], h1_t[NLEV], h2_t[NLEV], qlo_t[NLEV];

        two_row_step<NLEV, FIRST, WRITE_Y, FINAL, 0>(
            t, r0, r1, ip, sum_in, sum_out, y_out, pbase,
            col, warp, isL, isR, eE,
            pA_s, pB_s, h1_s, h2_s, qlo_s, qhiA,
            pA_t, pB_t, h1_t, h2_t, qlo_t);

        two_row_step<NLEV, FIRST, WRITE_Y, FINAL, 1>(
            t + 2, r0, r1, ip, sum_in, sum_out, y_out, pbase,
            col, warp, isL, isR, eE,
            pA_t, pB_t, h1_t, h2_t, qlo_t, qhiB,
            pA_s, pB_s, h1_s, h2_s, qlo_s);
    }
}

extern "C" void kernel_launch(void* const* d_in, const int* in_sizes, int n_in,
                              void* d_out, int out_size)
{
    const float* in = (const float*)d_in[0];
    float* out      = (float*)d_out;

    const int planes = in_sizes[0] / (IMH * IMW);   // 96

    float *scrA = nullptr, *scrB = nullptr;
    cudaGetSymbolAddress((void**)&scrA, g_scrA);
    cudaGetSymbolAddress((void**)&scrB, g_scrB);

    dim3 grid(planes, SEGS);

    // Pass 1: levels 1..7 (+ identity term), writes s(0..7) and y7.
    blur_pass_kernel<7, true,  true,  false><<<grid, TPB>>>(in,   nullptr, out, scrA);
    // Pass 2: levels 8..14, accumulates into out, writes y14.
    blur_pass_kernel<7, false, true,  false><<<grid, TPB>>>(scrA, out,     out, scrB);
    // Pass 3: levels 15..19, accumulates and scales by 1/20.
    blur_pass_kernel<5, false, false, true ><<<grid, TPB>>>(scrB, out,     out, nullptr);
}

// round 13
// speedup vs baseline: 1.9318x; 1.9318x over previous
#include <cuda_runtime.h>
#include <cuda_fp16.h>

// BlurOutwards: out = (1/20) * sum_{i=0}^{19} D^i(x), D = 3x3 max, zero padding.
// Iterated zero-padded dilation == iterated 3x3 max on the zero-extended image;
// composes across passes: D^{a+b}(x) = D^b(D^a(x)).
//
// R11 structure (3 passes 7+7+5, 1 px/thread, TPB=512, 2 CTAs/SM, two rows
// per barrier, corner-square identity, in-place state rotation) with the
// DILATION STREAM IN PACKED half2 (rows t,t+1 share one 32-bit register):
//   - max ops are exact in fp16; only a one-time input quantization error
//     (<= 2^-11 rel) enters the 19 dilated terms. The identity term and all
//     summation stay in fp32.
//   - 2 SHFL per level (was 4), HMNMX2 halves max-instr count, 32-bit edge
//     LDS/STS (was 64), packed state halves register pressure.

#define IMH   512
#define IMW   512
#define TPB   512
#define NW    (TPB / 32)       // 16 warps
#define SEGS  3
#define MAX_PLANES 96

// fp16 scratch for intermediate dilation planes (y7, y14).
__device__ __half g_scrA[MAX_PLANES * IMH * IMW];
__device__ __half g_scrB[MAX_PLANES * IMH * IMW];

template<int NLEV, bool FIRST, bool WRITE_Y, bool FINAL>
__global__ __launch_bounds__(TPB, 2)
void blur_pass_kernel(const float* __restrict__ inF,   // FIRST pass input
                      const __half* __restrict__ inH,  // later pass input
                      const float* sum_in,
                      float* sum_out,
                      __half* __restrict__ y_out)
{
    const int plane = blockIdx.x;
    const int seg   = blockIdx.y;

    const int r0 = (IMH * seg) / SEGS;
    const int r1 = (IMH * (seg + 1)) / SEGS;

    const size_t pbase = (size_t)plane * IMH * IMW;
    const float* ipF = FIRST ? (inF + pbase) : nullptr;
    const __half* ipH = FIRST ? nullptr : (inH + pbase);

    const int col  = threadIdx.x;
    const int lane = col & 31;
    const int warp = col >> 5;
    const bool isL = (lane == 0);
    const bool isR = (lane == 31);

    // Edge exchange: [parity][side][warpSlot][level], uint = half2 (rowA,rowB)
    //   side 0 = right edges (lane31), side 1 = left edges (lane0).
    //   warpSlot = warp+1; slots 0 and NW+1 stay zero (image-border guard;
    //   0x0 bits == half2(+0,+0), the correct padding value).
    __shared__ unsigned eE[2][2][NW + 2][8];
    for (int k = threadIdx.x; k < 2 * 2 * (NW + 2) * 8; k += TPB)
        (&eE[0][0][0][0])[k] = 0u;
    __syncthreads();

    // Per-level state (zero == zero-extension above the strip):
    //   pend: packed input row pair (2 rows stale)
    //   hv:   packed (H[k-2], H[k-1])
    //   dq*:  fp32 3-row delay of the partial-sum stream
    unsigned pend[NLEV], hv[NLEV];
    float dq1lo[NLEV], dq1hi[NLEV], dq2hi[NLEV];
#pragma unroll
    for (int i = 0; i < NLEV; ++i) {
        pend[i] = 0u; hv[i] = 0u;
        dq1lo[i] = 0.f; dq1hi[i] = 0.f; dq2hi[i] = 0.f;
    }

    const int DELAY = 3 * NLEV;
    const int T0    = r0 - NLEV;              // spatial warmup

    int par = 0;
    for (int t = T0; t - DELAY <= r1 - 1; t += 2, par ^= 1) {
        unsigned (*eRd)[NW + 2][8] = eE[par];
        unsigned (*eWr)[NW + 2][8] = eE[par ^ 1];

        // Ingest input rows t, t+1 (zero-extended).
        unsigned u;        // packed half2 (rowA, rowB) dilation stream
        float q0, q1;      // fp32 partial-sum stream
        if (FIRST) {
            float u0 = 0.0f, u1 = 0.0f;
            if ((unsigned)t       < (unsigned)IMH) u0 = ipF[(size_t)t       * IMW + col];
            if ((unsigned)(t + 1) < (unsigned)IMH) u1 = ipF[(size_t)(t + 1) * IMW + col];
            __half2 up = __floats2half2_rn(u0, u1);
            u = *(unsigned*)&up;
            q0 = u0;  q1 = u1;    // identity term in exact fp32
        } else {
            __half v0 = __ushort_as_half((unsigned short)0);
            __half v1 = v0;
            if ((unsigned)t       < (unsigned)IMH) v0 = ipH[(size_t)t       * IMW + col];
            if ((unsigned)(t + 1) < (unsigned)IMH) v1 = ipH[(size_t)(t + 1) * IMW + col];
            __half2 up = __halves2half2(v0, v1);
            u = *(unsigned*)&up;
            q0 = 0.0f;  q1 = 0.0f;
        }

#pragma unroll
        for (int i = 0; i < NLEV; ++i) {
            unsigned a  = pend[i];
            unsigned lu = __shfl_up_sync(0xffffffffu, a, 1);
            unsigned ru = __shfl_down_sync(0xffffffffu, a, 1);
            if (isL) lu = eRd[0][warp][i];
            if (isR) ru = eRd[1][warp + 2][i];
            __half2 l2 = *(__half2*)&lu;
            __half2 r2 = *(__half2*)&ru;
            __half2 hvp = *(__half2*)&hv[i];

            __half2 H, y;
            if (FIRST && i == 0) {
                // Raw-image level: full separable 3x3 max.
                __half2 p2 = *(__half2*)&a;
                H = __hmax2(__hmax2(l2, r2), p2);
                __half2 t1 = __hmax2(hvp, H);                       // (Hk-2|Hk, Hk-1|Hk+1)
                __half2 sh = __halves2half2(__high2half(hvp),
                                            __low2half(H));        // (Hk-1, Hk)
                y = __hmax2(t1, sh);
            } else {
                // Corner identity: input is already a square max (radius >= 1).
                H = __hmax2(l2, r2);
                y = __hmax2(hvp, H);   // (max(Hk-2,Hk), max(Hk-1,Hk+1))
            }
            hv[i] = *(unsigned*)&H;

            // Sum stream in fp32, delayed 3 rows to align with (yA, yB).
            float yA = __low2float(y);
            float yB = __high2float(y);
            float sA = dq2hi[i] + yA;
            float sB = dq1lo[i] + yB;
            dq2hi[i] = dq1hi[i];
            dq1hi[i] = q1;
            dq1lo[i] = q0;

            // Hand-off to next level + edge publication for next iteration.
            pend[i] = u;
            if (isL) eWr[1][warp + 1][i] = u;
            if (isR) eWr[0][warp + 1][i] = u;
            u  = *(unsigned*)&y;
            q0 = sA;  q1 = sB;
        }

        // q0/q1 = s_NLEV rows (t-DELAY, t+1-DELAY); u = packed y_NLEV same rows.
        const int orow = t - DELAY;
        __half2 yfin = *(__half2*)&u;
        if (orow >= r0 && orow < r1) {
            const size_t idx = pbase + (size_t)orow * IMW + col;
            float s = q0;
            if (!FIRST) s += sum_in[idx];
            sum_out[idx] = FINAL ? s * 0.05f : s;
            if (WRITE_Y) y_out[idx] = __low2half(yfin);
        }
        const int orow2 = orow + 1;
        if (orow2 >= r0 && orow2 < r1) {
            const size_t idx = pbase + (size_t)orow2 * IMW + col;
            float s = q1;
            if (!FIRST) s += sum_in[idx];
            sum_out[idx] = FINAL ? s * 0.05f : s;
            if (WRITE_Y) y_out[idx] = __high2half(yfin);
        }

        __syncthreads();  // separates this iteration's edge writes from next reads
    }
}

extern "C" void kernel_launch(void* const* d_in, const int* in_sizes, int n_in,
                              void* d_out, int out_size)
{
    const float* in = (const float*)d_in[0];
    float* out      = (float*)d_out;

    const int planes = in_sizes[0] / (IMH * IMW);   // 96

    __half *scrA = nullptr, *scrB = nullptr;
    cudaGetSymbolAddress((void**)&scrA, g_scrA);
    cudaGetSymbolAddress((void**)&scrB, g_scrB);

    dim3 grid(planes, SEGS);

    // Pass 1: levels 1..7 (+ identity term in fp32), writes s(0..7) and y7 (fp16).
    blur_pass_kernel<7, true,  true,  false><<<grid, TPB>>>(in,   nullptr, nullptr, out, scrA);
    // Pass 2: levels 8..14, accumulates into out, writes y14 (fp16).
    blur_pass_kernel<7, false, true,  false><<<grid, TPB>>>(nullptr, scrA, out,     out, scrB);
    // Pass 3: levels 15..19, accumulates and scales by 1/20.
    blur_pass_kernel<5, false, false, true ><<<grid, TPB>>>(nullptr, scrB, out,     out, nullptr);
}

// round 15
// speedup vs baseline: 2.2600x; 1.1699x over previous
#include <cuda_runtime.h>
#include <cuda_fp16.h>

// BlurOutwards: out = (1/20) * sum_{i=0}^{19} D^i(x), D = 3x3 max, zero padding.
// Iterated zero-padded dilation == iterated 3x3 max on the zero-extended image;
// composes across passes: D^{a+b}(x) = D^b(D^a(x)).
//
// TWO chained register-pipeline passes (10 + 9 levels), 1 px/thread, TPB=512,
// 2 CTAs/SM, two rows per barrier, corner-square identity. BOTH the dilation
// stream and the per-pass partial-sum stream are packed half2 (rows t, t+1 in
// one register):
//   - max ops exact in fp16; per-pass fp16 accumulation is <= 11 terms with
//     the cross-pass accumulation done in fp32 (pass 1 stores fp32 partials).
//   - per level: 2 SHFL, 1-2 HMNMX2, 1 PRMT + 1 HADD2 for the 3-row-delayed
//     sum, 32-bit edge LDS/STS. State = 4 regs/level -> 10 levels fit 64 regs.

#define IMH   512
#define IMW   512
#define TPB   512
#define NW    (TPB / 32)       // 16 warps
#define SEGS  3
#define MAX_PLANES 96

// fp16 scratch for the intermediate dilation plane (y10).
__device__ __half g_scrA[MAX_PLANES * IMH * IMW];

template<int NLEV, bool FIRST, bool FINAL>
__global__ __launch_bounds__(TPB, 2)
void blur_pass_kernel(const float* __restrict__ inF,   // FIRST pass input
                      const __half* __restrict__ inH,  // later pass input
                      const float* sum_in,
                      float* sum_out,
                      __half* __restrict__ y_out)
{
    const int plane = blockIdx.x;
    const int seg   = blockIdx.y;

    const int r0 = (IMH * seg) / SEGS;
    const int r1 = (IMH * (seg + 1)) / SEGS;

    const size_t pbase = (size_t)plane * IMH * IMW;
    const float*  ipF = FIRST ? (inF + pbase) : nullptr;
    const __half* ipH = FIRST ? nullptr : (inH + pbase);

    const int col  = threadIdx.x;
    const int lane = col & 31;
    const int warp = col >> 5;
    const bool isL = (lane == 0);
    const bool isR = (lane == 31);

    // Edge exchange: [parity][side][warpSlot][level], uint = half2 (rowA,rowB)
    //   side 0 = right edges (lane31), side 1 = left edges (lane0).
    //   warpSlot = warp+1; slots 0 and NW+1 stay zero (image-border guard;
    //   0x0 bits == half2(+0,+0), the correct padding value).
    __shared__ unsigned eE[2][2][NW + 2][NLEV];
    for (int k = threadIdx.x; k < 2 * 2 * (NW + 2) * NLEV; k += TPB)
        (&eE[0][0][0][0])[k] = 0u;
    __syncthreads();

    // Per-level state (zero == zero-extension above the strip):
    //   pend: packed input row pair (2 rows stale)
    //   hv:   packed (H[k-2], H[k-1])
    //   D1/D2: packed sum-stream packs from 1 and 2 iterations ago
    //          (3-row delay realized as addend = (D2.hi, D1.lo))
    unsigned pend[NLEV], hv[NLEV], D1[NLEV], D2[NLEV];
#pragma unroll
    for (int i = 0; i < NLEV; ++i) {
        pend[i] = 0u; hv[i] = 0u; D1[i] = 0u; D2[i] = 0u;
    }

    const int DELAY = 3 * NLEV;
    const int T0    = r0 - NLEV;              // spatial warmup

    int par = 0;
    for (int t = T0; t - DELAY <= r1 - 1; t += 2, par ^= 1) {
        unsigned (*eRd)[NW + 2][NLEV] = eE[par];
        unsigned (*eWr)[NW + 2][NLEV] = eE[par ^ 1];

        // Ingest input rows t, t+1 (zero-extended), packed half2.
        unsigned u;
        if (FIRST) {
            float u0 = 0.0f, u1 = 0.0f;
            if ((unsigned)t       < (unsigned)IMH) u0 = ipF[(size_t)t       * IMW + col];
            if ((unsigned)(t + 1) < (unsigned)IMH) u1 = ipF[(size_t)(t + 1) * IMW + col];
            __half2 up = __floats2half2_rn(u0, u1);
            u = *(unsigned*)&up;
        } else {
            __half v0 = __ushort_as_half((unsigned short)0), v1 = v0;
            if ((unsigned)t       < (unsigned)IMH) v0 = ipH[(size_t)t       * IMW + col];
            if ((unsigned)(t + 1) < (unsigned)IMH) v1 = ipH[(size_t)(t + 1) * IMW + col];
            __half2 up = __halves2half2(v0, v1);
            u = *(unsigned*)&up;
        }
        // Partial-sum stream pack: identity term on pass 1, zero otherwise.
        __half2 Q = FIRST ? *(__half2*)&u
                          : __halves2half2(__ushort_as_half(0), __ushort_as_half(0));

#pragma unroll
        for (int i = 0; i < NLEV; ++i) {
            unsigned a  = pend[i];
            unsigned lu = __shfl_up_sync(0xffffffffu, a, 1);
            unsigned ru = __shfl_down_sync(0xffffffffu, a, 1);
            if (isL) lu = eRd[0][warp][i];
            if (isR) ru = eRd[1][warp + 2][i];
            __half2 l2  = *(__half2*)&lu;
            __half2 r2  = *(__half2*)&ru;
            __half2 hvp = *(__half2*)&hv[i];

            __half2 H, y;
            if (FIRST && i == 0) {
                // Raw-image level: full separable 3x3 max.
                __half2 p2 = *(__half2*)&a;
                H = __hmax2(__hmax2(l2, r2), p2);
                __half2 t1 = __hmax2(hvp, H);
                __half2 sh = __halves2half2(__high2half(hvp), __low2half(H));
                y = __hmax2(t1, sh);
            } else {
                // Corner identity: input is already a square max (radius >= 1).
                H = __hmax2(l2, r2);
                y = __hmax2(hvp, H);   // (max(Hk-2,Hk), max(Hk-1,Hk+1))
            }
            hv[i] = *(unsigned*)&H;

            // Sum stream, 3-row delay per level: addend = (D2.hi, D1.lo).
            __half2 d1 = *(__half2*)&D1[i];
            __half2 d2 = *(__half2*)&D2[i];
            __half2 add = __halves2half2(__high2half(d2), __low2half(d1));
            __half2 S = __hadd2(add, y);
            D2[i] = D1[i];
            D1[i] = *(unsigned*)&Q;

            // Hand-off to next level + edge publication for next iteration.
            pend[i] = u;
            if (isL) eWr[1][warp + 1][i] = u;
            if (isR) eWr[0][warp + 1][i] = u;
            u = *(unsigned*)&y;
            Q = S;
        }

        // Q = s_NLEV rows (t-DELAY, t+1-DELAY); u = packed y_NLEV same rows.
        const int orow = t - DELAY;
        __half2 yfin = *(__half2*)&u;
        if (orow >= r0 && orow < r1) {
            const size_t idx = pbase + (size_t)orow * IMW + col;
            float s = __low2float(Q);
            if (!FIRST) s += sum_in[idx];
            sum_out[idx] = FINAL ? s * 0.05f : s;
            if (FIRST) y_out[idx] = __low2half(yfin);
        }
        const int orow2 = orow + 1;
        if (orow2 >= r0 && orow2 < r1) {
            const size_t idx = pbase + (size_t)orow2 * IMW + col;
            float s = __high2float(Q);
            if (!FIRST) s += sum_in[idx];
            sum_out[idx] = FINAL ? s * 0.05f : s;
            if (FIRST) y_out[idx] = __high2half(yfin);
        }

        __syncthreads();  // separates this iteration's edge writes from next reads
    }
}

extern "C" void kernel_launch(void* const* d_in, const int* in_sizes, int n_in,
                              void* d_out, int out_size)
{
    const float* in = (const float*)d_in[0];
    float* out      = (float*)d_out;

    const int planes = in_sizes[0] / (IMH * IMW);   // 96

    __half* scrA = nullptr;
    cudaGetSymbolAddress((void**)&scrA, g_scrA);

    dim3 grid(planes, SEGS);

    // Pass 1: identity + levels 1..10; writes fp32 partial sum and y10 (fp16).
    blur_pass_kernel<10, true,  false><<<grid, TPB>>>(in, nullptr, nullptr, out, scrA);
    // Pass 2: levels 11..19; adds to the fp32 partial sum and scales by 1/20.
    blur_pass_kernel<9,  false, true ><<<grid, TPB>>>(nullptr, scrA, out,    out, nullptr);
}

// round 16
// speedup vs baseline: 2.7131x; 1.2005x over previous
#include <cuda_runtime.h>
#include <cuda_fp16.h>

// BlurOutwards: out = (1/20) * sum_{i=0}^{19} D^i(x), D = 3x3 max, zero padding.
// Iterated zero-padded dilation == iterated 3x3 max on the zero-extended image;
// composes across passes: D^{a+b}(x) = D^b(D^a(x)).
//
// TWO chained register-pipeline passes (10 + 9 levels), 1 px/thread, TPB=512,
// 2 CTAs/SM, two rows per barrier, corner-square identity, dilation + per-pass
// sum streams in packed half2 (R15 semantics), plus:
//   - one-iteration-ahead software prefetch of the input rows and (pass 2)
//     the fp32 partial-sum pair, so LDG latency is off the critical path;
//   - the intermediate y10 plane stored ROW-PAIR-PACKED (uint = half2(2k,2k+1)):
//     pass 1 writes one STG.32, pass 2 reads one LDG.32. Even segment
//     boundaries {0,172,344,512} + even T0 keep packs aligned.

#define IMH   512
#define IMW   512
#define TPB   512
#define NW    (TPB / 32)       // 16 warps
#define MAX_PLANES 96

// Row-pair-packed fp16 scratch: [plane][rowPair][col], uint = half2(rowA,rowB).
__device__ unsigned g_scrP[MAX_PLANES * (IMH / 2) * IMW];

__device__ __constant__ int SEG_R[4] = {0, 172, 344, 512};  // even boundaries

template<int NLEV, bool FIRST, bool FINAL>
__global__ __launch_bounds__(TPB, 2)
void blur_pass_kernel(const float* __restrict__ inF,      // FIRST pass input
                      const unsigned* __restrict__ inP,   // packed fp16 input
                      const float* sum_in,
                      float* sum_out,
                      unsigned* __restrict__ y_out)       // packed fp16 output
{
    const int plane = blockIdx.x;
    const int seg   = blockIdx.y;
    const int r0 = SEG_R[seg];
    const int r1 = SEG_R[seg + 1];

    const size_t pbase  = (size_t)plane * IMH * IMW;            // fp32 planes
    const size_t ppbase = (size_t)plane * (IMH / 2) * IMW;      // packed planes
    const float*    ipF = FIRST ? (inF + pbase) : nullptr;
    const unsigned* ipP = FIRST ? nullptr : (inP + ppbase);

    const int col  = threadIdx.x;
    const int lane = col & 31;
    const int warp = col >> 5;
    const bool isL = (lane == 0);
    const bool isR = (lane == 31);

    // Edge exchange: [parity][side][warpSlot][level], uint = half2 (rowA,rowB)
    //   side 0 = right edges (lane31), side 1 = left edges (lane0).
    //   warpSlot = warp+1; slots 0 and NW+1 stay zero (0x0 == half2(+0,+0)).
    __shared__ unsigned eE[2][2][NW + 2][NLEV];
    for (int k = threadIdx.x; k < 2 * 2 * (NW + 2) * NLEV; k += TPB)
        (&eE[0][0][0][0])[k] = 0u;
    __syncthreads();

    // Per-level state (zero == zero-extension above the strip).
    unsigned pend[NLEV], hv[NLEV], D1[NLEV], D2[NLEV];
#pragma unroll
    for (int i = 0; i < NLEV; ++i) {
        pend[i] = 0u; hv[i] = 0u; D1[i] = 0u; D2[i] = 0u;
    }

    const int DELAY = 3 * NLEV;
    const int T0    = (r0 - NLEV) & ~1;       // even warmup start (superset-safe)

    // ---- prefetch machinery (one iteration ahead) ----
    float    pf0 = 0.f, pf1 = 0.f;   // FIRST: raw fp32 rows
    unsigned pu  = 0u;               // !FIRST: packed fp16 row pair
    float    ps0 = 0.f, ps1 = 0.f;   // !FIRST: fp32 partial-sum pair

    auto pref = [&](int tn) {
        if (FIRST) {
            pf0 = ((unsigned)tn       < (unsigned)IMH) ? __ldg(&ipF[(size_t)tn       * IMW + col]) : 0.f;
            pf1 = ((unsigned)(tn + 1) < (unsigned)IMH) ? __ldg(&ipF[(size_t)(tn + 1) * IMW + col]) : 0.f;
        } else {
            pu = ((unsigned)tn < (unsigned)IMH) ? __ldg(&ipP[(size_t)(tn >> 1) * IMW + col]) : 0u;
            const int o0 = tn - DELAY, o1 = o0 + 1;
            ps0 = (o0 >= r0 && o0 < r1) ? __ldg(&sum_in[pbase + (size_t)o0 * IMW + col]) : 0.f;
            ps1 = (o1 >= r0 && o1 < r1) ? __ldg(&sum_in[pbase + (size_t)o1 * IMW + col]) : 0.f;
        }
    };
    pref(T0);

    int par = 0;
    for (int t = T0; t - DELAY <= r1 - 1; t += 2, par ^= 1) {
        unsigned (*eRd)[NW + 2][NLEV] = eE[par];
        unsigned (*eWr)[NW + 2][NLEV] = eE[par ^ 1];

        // Consume prefetched values, then immediately prefetch the next pair.
        unsigned u;
        if (FIRST) {
            __half2 up = __floats2half2_rn(pf0, pf1);
            u = *(unsigned*)&up;
        } else {
            u = pu;
        }
        const float si0 = ps0, si1 = ps1;
        pref(t + 2);

        __half2 Q = FIRST ? *(__half2*)&u
                          : __halves2half2(__ushort_as_half(0), __ushort_as_half(0));

#pragma unroll
        for (int i = 0; i < NLEV; ++i) {
            unsigned a  = pend[i];
            unsigned lu = __shfl_up_sync(0xffffffffu, a, 1);
            unsigned ru = __shfl_down_sync(0xffffffffu, a, 1);
            if (isL) lu = eRd[0][warp][i];
            if (isR) ru = eRd[1][warp + 2][i];
            __half2 l2  = *(__half2*)&lu;
            __half2 r2  = *(__half2*)&ru;
            __half2 hvp = *(__half2*)&hv[i];

            __half2 H, y;
            if (FIRST && i == 0) {
                // Raw-image level: full separable 3x3 max.
                __half2 p2 = *(__half2*)&a;
                H = __hmax2(__hmax2(l2, r2), p2);
                __half2 t1 = __hmax2(hvp, H);
                __half2 sh = __halves2half2(__high2half(hvp), __low2half(H));
                y = __hmax2(t1, sh);
            } else {
                // Corner identity: input is already a square max (radius >= 1).
                H = __hmax2(l2, r2);
                y = __hmax2(hvp, H);   // (max(Hk-2,Hk), max(Hk-1,Hk+1))
            }
            hv[i] = *(unsigned*)&H;

            // Sum stream, 3-row delay per level: addend = (D2.hi, D1.lo).
            __half2 d1 = *(__half2*)&D1[i];
            __half2 d2 = *(__half2*)&D2[i];
            __half2 add = __halves2half2(__high2half(d2), __low2half(d1));
            __half2 S = __hadd2(add, y);
            D2[i] = D1[i];
            D1[i] = *(unsigned*)&Q;

            // Hand-off to next level + edge publication for next iteration.
            pend[i] = u;
            if (isL) eWr[1][warp + 1][i] = u;
            if (isR) eWr[0][warp + 1][i] = u;
            u = *(unsigned*)&y;
            Q = S;
        }

        // Q = s_NLEV rows (t-DELAY, t+1-DELAY); u = packed y_NLEV same rows.
        const int orow = t - DELAY;
        if (FIRST) {
            // orow even, r0/r1 even: both rows in or out together.
            if (orow >= r0 && orow < r1) {
                const size_t idx = pbase + (size_t)orow * IMW + col;
                sum_out[idx]       = __low2float(Q);
                sum_out[idx + IMW] = __high2float(Q);
                y_out[ppbase + (size_t)(orow >> 1) * IMW + col] = u;  // packed y_NLEV
            }
        } else {
            if (orow >= r0 && orow < r1) {
                const size_t idx = pbase + (size_t)orow * IMW + col;
                float s = si0 + __low2float(Q);
                sum_out[idx] = FINAL ? s * 0.05f : s;
            }
            const int orow2 = orow + 1;
            if (orow2 >= r0 && orow2 < r1) {
                const size_t idx = pbase + (size_t)orow2 * IMW + col;
                float s = si1 + __high2float(Q);
                sum_out[idx] = FINAL ? s * 0.05f : s;
            }
        }

        __syncthreads();  // separates this iteration's edge writes from next reads
    }
}

extern "C" void kernel_launch(void* const* d_in, const int* in_sizes, int n_in,
                              void* d_out, int out_size)
{
    const float* in = (const float*)d_in[0];
    float* out      = (float*)d_out;

    const int planes = in_sizes[0] / (IMH * IMW);   // 96

    unsigned* scrP = nullptr;
    cudaGetSymbolAddress((void**)&scrP, g_scrP);

    dim3 grid(planes, 3);

    // Pass 1: identity + levels 1..10; writes fp32 partial sum and packed y10.
    blur_pass_kernel<10, true,  false><<<grid, TPB>>>(in, nullptr, nullptr, out, scrP);
    // Pass 2: levels 11..19; adds to the fp32 partial sum and scales by 1/20.
    blur_pass_kernel<9,  false, true ><<<grid, TPB>>>(nullptr, scrP, out,    out, nullptr);
}